// round 13
// baseline (speedup 1.0000x reference)
#include <cuda_runtime.h>
#include <cstdint>
#include <cstddef>

// SGCEvaluator: N=100000, E=1600000, D=128, C=40, 2 hops.
// (A^2 X) W + b == A^2 (X W) + b  -> project FIRST, hop on 40 dims.
// Normalization factored into per-NODE diagonal scales (rsqrt on the fly):
//   A^2 h0 = R_in * Wraw * (R_in R_out) * Wraw * (R_out * h0)
#define N_NODES 100000
#define N_EDGES 1600000
#define D_FEAT  128
#define N_CLASS 40
#define MAX_DEG 64   // P(in-deg >= 64 | Poisson(16)) ~ 1e-18 per node

// Single contiguous meta slab -> ONE memset:
//   [0, N) float deg_out | [N, 2N) float deg_in | [2N, 3N) int cnt
__device__ __align__(256) unsigned g_meta[3 * N_NODES];
__device__ __align__(256) int2  g_csr[(size_t)N_NODES * MAX_DEG];  // (src, raw ew)
__device__ __align__(256) float g_h0 [(size_t)N_NODES * N_CLASS];
__device__ __align__(256) float g_h1 [(size_t)N_NODES * N_CLASS];

__device__ __forceinline__ float* deg_out_ptr() { return (float*)g_meta; }
__device__ __forceinline__ float* deg_in_ptr()  { return (float*)g_meta + N_NODES; }
__device__ __forceinline__ int*   cnt_ptr()     { return (int*)g_meta + 2 * N_NODES; }

__device__ __forceinline__ float guarded_rsqrt(float v)
{
    return (v > 0.f) ? rsqrtf(v) : 0.f;
}

// ---------------------------------------------------------------------------
// 1) Degrees + inverted-adjacency build in ONE edge pass (R9 form).
// ---------------------------------------------------------------------------
__global__ void deg_fill_kernel(const int* __restrict__ src,
                                const int* __restrict__ dst,
                                const float* __restrict__ ew,
                                int E)
{
    int e = blockIdx.x * blockDim.x + threadIdx.x;
    if (e >= E) return;

    int   s = src[e];
    int   d = dst[e];
    float w = ew[e];

    atomicAdd(deg_out_ptr() + s, w);
    atomicAdd(deg_in_ptr()  + d, w);

    int pos = atomicAdd(cnt_ptr() + d, 1);
    if (pos < MAX_DEG)
        g_csr[(size_t)d * MAX_DEG + pos] = make_int2(s, __float_as_int(w));
}

// ---------------------------------------------------------------------------
// 2) X' = X @ W : 8x8 register tiles, double-buffered k-staging.
// ---------------------------------------------------------------------------
#define XW_M    256
#define XW_T    160
#define XW_KT   16
#define XW_ROW  260
#define XW_NF4  (XW_M * XW_KT / 4)            // 1024 float4 per stage
#define XW_RPT  ((XW_NF4 + XW_T - 1) / XW_T)  // 7

__global__ void __launch_bounds__(XW_T)
xw_kernel(const float* __restrict__ x,
          const float* __restrict__ W,
          float* __restrict__ xp,
          int N)
{
    __shared__ float Ws[D_FEAT * N_CLASS];
    __shared__ float xs[2][XW_KT][XW_ROW];

    const int t    = threadIdx.x;
    const int tx   = t >> 5;
    const int ty   = t & 31;
    const int nblk = blockIdx.x * XW_M;

    for (int i = t; i < D_FEAT * N_CLASS / 4; i += XW_T)
        ((float4*)Ws)[i] = ((const float4*)W)[i];

    float acc[8][8];
#pragma unroll
    for (int i = 0; i < 8; i++)
#pragma unroll
        for (int j = 0; j < 8; j++) acc[i][j] = 0.f;

    const float4* x4 = (const float4*)x;
    float4 tmp[XW_RPT];

    auto FETCH = [&](int kt) {
#pragma unroll
        for (int r = 0; r < XW_RPT; r++) {
            int j = t + r * XW_T;
            if (j < XW_NF4) {
                int n  = j >> 2;
                int kq = j & 3;
                int nn = nblk + n;
                tmp[r] = (nn < N) ? x4[(size_t)nn * 32 + kt * 4 + kq]
                                  : make_float4(0.f, 0.f, 0.f, 0.f);
            }
        }
    };
    auto STORE = [&](int buf) {
#pragma unroll
        for (int r = 0; r < XW_RPT; r++) {
            int j = t + r * XW_T;
            if (j < XW_NF4) {
                int n  = j >> 2;
                int kq = j & 3;
                xs[buf][kq * 4 + 0][n] = tmp[r].x;
                xs[buf][kq * 4 + 1][n] = tmp[r].y;
                xs[buf][kq * 4 + 2][n] = tmp[r].z;
                xs[buf][kq * 4 + 3][n] = tmp[r].w;
            }
        }
    };

    FETCH(0);
    STORE(0);
    __syncthreads();

    int buf = 0;
    for (int kt = 0; kt < D_FEAT / XW_KT; kt++) {
        if (kt < D_FEAT / XW_KT - 1) FETCH(kt + 1);

#pragma unroll
        for (int kk = 0; kk < XW_KT; kk++) {
            float4 a0 = *(const float4*)&xs[buf][kk][ty * 4];
            float4 a1 = *(const float4*)&xs[buf][kk][128 + ty * 4];
            const float* wr = &Ws[(kt * XW_KT + kk) * N_CLASS + tx * 8];
            float4 w0 = *(const float4*)(wr);
            float4 w1 = *(const float4*)(wr + 4);
            float xm[8] = {a0.x, a0.y, a0.z, a0.w, a1.x, a1.y, a1.z, a1.w};
            float wv[8] = {w0.x, w0.y, w0.z, w0.w, w1.x, w1.y, w1.z, w1.w};
#pragma unroll
            for (int i = 0; i < 8; i++)
#pragma unroll
                for (int j = 0; j < 8; j++)
                    acc[i][j] += xm[i] * wv[j];
        }

        if (kt < D_FEAT / XW_KT - 1) STORE(buf ^ 1);
        __syncthreads();
        buf ^= 1;
    }

#pragma unroll
    for (int i = 0; i < 8; i++) {
        int n = nblk + ((i < 4) ? (ty * 4 + i) : (128 + ty * 4 + i - 4));
        if (n < N) {
            float* o = xp + (size_t)n * N_CLASS + tx * 8;
            *(float4*)(o)     = make_float4(acc[i][0], acc[i][1], acc[i][2], acc[i][3]);
            *(float4*)(o + 4) = make_float4(acc[i][4], acc[i][5], acc[i][6], acc[i][7]);
        }
    }
}

// ---------------------------------------------------------------------------
// 3) Row scale: h0[n][*] *= rsqrt(deg_out[n])
// ---------------------------------------------------------------------------
__global__ void prescale_kernel(float* __restrict__ h, int N)
{
    int i = blockIdx.x * blockDim.x + threadIdx.x;       // float4 index
    int total = N * (N_CLASS / 4);
    if (i >= total) return;
    int n = i / (N_CLASS / 4);
    float sc = guarded_rsqrt(__ldg(deg_out_ptr() + n));
    float4 v = ((float4*)h)[i];
    v.x *= sc; v.y *= sc; v.z *= sc; v.w *= sc;
    ((float4*)h)[i] = v;
}

// ---------------------------------------------------------------------------
// 4) Pull-style hop, DOUBLE-WIDE threads: thread = (dst, 2 float4s).
//    5 threads/dst; per edge-pair each thread issues 1 list load + 4
//    independent gathers into 2 independent accumulator chains (2x MLP of
//    the single-float4 variant). Plain unroll-4 loads (ptxas batches).
// ---------------------------------------------------------------------------
#define HOP_T 256

__global__ void __launch_bounds__(HOP_T)
hop_csr_kernel(const float* __restrict__ hin,
               float* __restrict__ hout,
               const float* __restrict__ bias,
               int mul_rs_out,     // 1 for hop1 (mid), 0 for final hop
               int N)
{
    int gtid = blockIdx.x * HOP_T + threadIdx.x;
    int d    = gtid / 5;
    int sub  = gtid - d * 5;       // 0..4 : owns float4 cols 2*sub, 2*sub+1
    if (d >= N) return;

    int cnt = __ldg(cnt_ptr() + d);
    cnt = (cnt > MAX_DEG) ? MAX_DEG : cnt;

    const int4* lst4 = (const int4*)&g_csr[(size_t)d * MAX_DEG];

    float4 acc0 = make_float4(0.f, 0.f, 0.f, 0.f);
    float4 acc1 = make_float4(0.f, 0.f, 0.f, 0.f);

    int pairs = cnt >> 1;
#pragma unroll 4
    for (int i = 0; i < pairs; i++) {
        int4 pp = __ldg(lst4 + i);               // (s0, w0, s1, w1) raw
        float w0 = __int_as_float(pp.y);
        float w1 = __int_as_float(pp.w);
        const float4* r0 = (const float4*)(hin + (size_t)pp.x * N_CLASS) + 2 * sub;
        const float4* r1 = (const float4*)(hin + (size_t)pp.z * N_CLASS) + 2 * sub;
        float4 u0 = __ldg(r0);
        float4 u1 = __ldg(r0 + 1);
        float4 t0 = __ldg(r1);
        float4 t1 = __ldg(r1 + 1);
        acc0.x += w0 * u0.x + w1 * t0.x;
        acc0.y += w0 * u0.y + w1 * t0.y;
        acc0.z += w0 * u0.z + w1 * t0.z;
        acc0.w += w0 * u0.w + w1 * t0.w;
        acc1.x += w0 * u1.x + w1 * t1.x;
        acc1.y += w0 * u1.y + w1 * t1.y;
        acc1.z += w0 * u1.z + w1 * t1.z;
        acc1.w += w0 * u1.w + w1 * t1.w;
    }
    if (cnt & 1) {
        int2 p = __ldg((const int2*)lst4 + (cnt - 1));
        float w = __int_as_float(p.y);
        const float4* r0 = (const float4*)(hin + (size_t)p.x * N_CLASS) + 2 * sub;
        float4 u0 = __ldg(r0);
        float4 u1 = __ldg(r0 + 1);
        acc0.x += w * u0.x; acc0.y += w * u0.y; acc0.z += w * u0.z; acc0.w += w * u0.w;
        acc1.x += w * u1.x; acc1.y += w * u1.y; acc1.z += w * u1.z; acc1.w += w * u1.w;
    }

    float sc = guarded_rsqrt(__ldg(deg_in_ptr() + d));
    if (mul_rs_out) sc *= guarded_rsqrt(__ldg(deg_out_ptr() + d));
    acc0.x *= sc; acc0.y *= sc; acc0.z *= sc; acc0.w *= sc;
    acc1.x *= sc; acc1.y *= sc; acc1.z *= sc; acc1.w *= sc;

    if (bias) {
        const float4* bv = (const float4*)bias + 2 * sub;
        float4 b0 = bv[0], b1 = bv[1];
        acc0.x += b0.x; acc0.y += b0.y; acc0.z += b0.z; acc0.w += b0.w;
        acc1.x += b1.x; acc1.y += b1.y; acc1.z += b1.z; acc1.w += b1.w;
    }

    float4* o = (float4*)(hout + (size_t)d * N_CLASS) + 2 * sub;
    o[0] = acc0;
    o[1] = acc1;
}

// ---------------------------------------------------------------------------
// Launch. Graph:
//   s :  memset(meta) -> fork -> deg_fill -> join -> prescale -> hop1 -> hop2
//   s2:               \-> xw -----------------^
// ---------------------------------------------------------------------------
extern "C" void kernel_launch(void* const* d_in, const int* in_sizes, int n_in,
                              void* d_out, int out_size)
{
    const float* features = (const float*)d_in[0];
    const int*   src      = (const int*)  d_in[1];
    const int*   dst      = (const int*)  d_in[2];
    const float* ew       = (const float*)d_in[3];
    const float* W        = (const float*)d_in[4];
    const float* b        = (const float*)d_in[5];
    float*       out      = (float*)d_out;

    const int E = in_sizes[1];
    const int N = in_sizes[0] / D_FEAT;

    void *p_meta, *p_h0, *p_h1;
    cudaGetSymbolAddress(&p_meta, g_meta);
    cudaGetSymbolAddress(&p_h0,   g_h0);
    cudaGetSymbolAddress(&p_h1,   g_h1);

    static cudaStream_t s2 = nullptr;
    static cudaEvent_t ev_fork = nullptr, ev_join = nullptr;
    if (s2 == nullptr) {
        cudaStreamCreateWithFlags(&s2, cudaStreamNonBlocking);
        cudaEventCreateWithFlags(&ev_fork, cudaEventDisableTiming);
        cudaEventCreateWithFlags(&ev_join, cudaEventDisableTiming);
    }

    cudaStream_t s = 0;
    const int T = 256;

    cudaMemsetAsync(p_meta, 0, (size_t)3 * N_NODES * sizeof(unsigned), s);

    // ---- fork ----
    cudaEventRecord(ev_fork, s);
    cudaStreamWaitEvent(s2, ev_fork, 0);

    // branch B: degrees + adjacency build (single edge pass)
    deg_fill_kernel<<<(E + T - 1) / T, T, 0, s>>>(src, dst, ew, E);

    // branch A: projection
    xw_kernel<<<(N + XW_M - 1) / XW_M, XW_T, 0, s2>>>(
        features, W, (float*)p_h0, N);

    // ---- join ----
    cudaEventRecord(ev_join, s2);
    cudaStreamWaitEvent(s, ev_join, 0);

    // pre-scale h0 rows by rsqrt(deg_out)
    {
        int total = N * (N_CLASS / 4);
        prescale_kernel<<<(total + T - 1) / T, T, 0, s>>>((float*)p_h0, N);
    }

    // hop 1 (mid): out-scale rs_in*rs_out ; hop 2 (final): rs_in, + bias
    int hop_threads = N * 5;
    int hop_blocks  = (hop_threads + HOP_T - 1) / HOP_T;
    hop_csr_kernel<<<hop_blocks, HOP_T, 0, s>>>(
        (const float*)p_h0, (float*)p_h1, nullptr, 1, N);
    hop_csr_kernel<<<hop_blocks, HOP_T, 0, s>>>(
        (const float*)p_h1, out, b, 0, N);
}

// round 14
// speedup vs baseline: 1.0872x; 1.0872x over previous
#include <cuda_runtime.h>
#include <cstdint>
#include <cstddef>

// SGCEvaluator: N=100000, E=1600000, D=128, C=40, 2 hops.
// (A^2 X) W + b == A^2 (X W) + b  -> project FIRST, hop on 40 dims.
// Normalization factored into per-NODE diagonal scales (rsqrt on the fly):
//   A^2 h0 = R_in * Wraw * (R_in R_out) * Wraw * (R_out * h0)
#define N_NODES 100000
#define N_EDGES 1600000
#define D_FEAT  128
#define N_CLASS 40
#define MAX_DEG 64   // P(in-deg >= 64 | Poisson(16)) ~ 1e-18 per node

// Single contiguous meta slab -> ONE memset:
//   [0, N) float deg_out | [N, 2N) float deg_in | [2N, 3N) int cnt
__device__ __align__(256) unsigned g_meta[3 * N_NODES];
__device__ __align__(256) int2  g_csr[(size_t)N_NODES * MAX_DEG];  // (src, raw ew)
__device__ __align__(256) float g_h0 [(size_t)N_NODES * N_CLASS];
__device__ __align__(256) float g_h1 [(size_t)N_NODES * N_CLASS];

__device__ __forceinline__ float* deg_out_ptr() { return (float*)g_meta; }
__device__ __forceinline__ float* deg_in_ptr()  { return (float*)g_meta + N_NODES; }
__device__ __forceinline__ int*   cnt_ptr()     { return (int*)g_meta + 2 * N_NODES; }

__device__ __forceinline__ float guarded_rsqrt(float v)
{
    return (v > 0.f) ? rsqrtf(v) : 0.f;
}

// ---------------------------------------------------------------------------
// 1) Degrees + inverted-adjacency build in ONE edge pass (R9 form).
// ---------------------------------------------------------------------------
__global__ void deg_fill_kernel(const int* __restrict__ src,
                                const int* __restrict__ dst,
                                const float* __restrict__ ew,
                                int E)
{
    int e = blockIdx.x * blockDim.x + threadIdx.x;
    if (e >= E) return;

    int   s = src[e];
    int   d = dst[e];
    float w = ew[e];

    atomicAdd(deg_out_ptr() + s, w);
    atomicAdd(deg_in_ptr()  + d, w);

    int pos = atomicAdd(cnt_ptr() + d, 1);
    if (pos < MAX_DEG)
        g_csr[(size_t)d * MAX_DEG + pos] = make_int2(s, __float_as_int(w));
}

// ---------------------------------------------------------------------------
// 2) X' = X @ W : 8x8 register tiles, double-buffered k-staging.
// ---------------------------------------------------------------------------
#define XW_M    256
#define XW_T    160
#define XW_KT   16
#define XW_ROW  260
#define XW_NF4  (XW_M * XW_KT / 4)            // 1024 float4 per stage
#define XW_RPT  ((XW_NF4 + XW_T - 1) / XW_T)  // 7

__global__ void __launch_bounds__(XW_T)
xw_kernel(const float* __restrict__ x,
          const float* __restrict__ W,
          float* __restrict__ xp,
          int N)
{
    __shared__ float Ws[D_FEAT * N_CLASS];
    __shared__ float xs[2][XW_KT][XW_ROW];

    const int t    = threadIdx.x;
    const int tx   = t >> 5;
    const int ty   = t & 31;
    const int nblk = blockIdx.x * XW_M;

    for (int i = t; i < D_FEAT * N_CLASS / 4; i += XW_T)
        ((float4*)Ws)[i] = ((const float4*)W)[i];

    float acc[8][8];
#pragma unroll
    for (int i = 0; i < 8; i++)
#pragma unroll
        for (int j = 0; j < 8; j++) acc[i][j] = 0.f;

    const float4* x4 = (const float4*)x;
    float4 tmp[XW_RPT];

    auto FETCH = [&](int kt) {
#pragma unroll
        for (int r = 0; r < XW_RPT; r++) {
            int j = t + r * XW_T;
            if (j < XW_NF4) {
                int n  = j >> 2;
                int kq = j & 3;
                int nn = nblk + n;
                tmp[r] = (nn < N) ? x4[(size_t)nn * 32 + kt * 4 + kq]
                                  : make_float4(0.f, 0.f, 0.f, 0.f);
            }
        }
    };
    auto STORE = [&](int buf) {
#pragma unroll
        for (int r = 0; r < XW_RPT; r++) {
            int j = t + r * XW_T;
            if (j < XW_NF4) {
                int n  = j >> 2;
                int kq = j & 3;
                xs[buf][kq * 4 + 0][n] = tmp[r].x;
                xs[buf][kq * 4 + 1][n] = tmp[r].y;
                xs[buf][kq * 4 + 2][n] = tmp[r].z;
                xs[buf][kq * 4 + 3][n] = tmp[r].w;
            }
        }
    };

    FETCH(0);
    STORE(0);
    __syncthreads();

    int buf = 0;
    for (int kt = 0; kt < D_FEAT / XW_KT; kt++) {
        if (kt < D_FEAT / XW_KT - 1) FETCH(kt + 1);

#pragma unroll
        for (int kk = 0; kk < XW_KT; kk++) {
            float4 a0 = *(const float4*)&xs[buf][kk][ty * 4];
            float4 a1 = *(const float4*)&xs[buf][kk][128 + ty * 4];
            const float* wr = &Ws[(kt * XW_KT + kk) * N_CLASS + tx * 8];
            float4 w0 = *(const float4*)(wr);
            float4 w1 = *(const float4*)(wr + 4);
            float xm[8] = {a0.x, a0.y, a0.z, a0.w, a1.x, a1.y, a1.z, a1.w};
            float wv[8] = {w0.x, w0.y, w0.z, w0.w, w1.x, w1.y, w1.z, w1.w};
#pragma unroll
            for (int i = 0; i < 8; i++)
#pragma unroll
                for (int j = 0; j < 8; j++)
                    acc[i][j] += xm[i] * wv[j];
        }

        if (kt < D_FEAT / XW_KT - 1) STORE(buf ^ 1);
        __syncthreads();
        buf ^= 1;
    }

#pragma unroll
    for (int i = 0; i < 8; i++) {
        int n = nblk + ((i < 4) ? (ty * 4 + i) : (128 + ty * 4 + i - 4));
        if (n < N) {
            float* o = xp + (size_t)n * N_CLASS + tx * 8;
            *(float4*)(o)     = make_float4(acc[i][0], acc[i][1], acc[i][2], acc[i][3]);
            *(float4*)(o + 4) = make_float4(acc[i][4], acc[i][5], acc[i][6], acc[i][7]);
        }
    }
}

// ---------------------------------------------------------------------------
// 3) Row scale: h0[n][*] *= rsqrt(deg_out[n])  (R9 form: 1 float4/thread)
// ---------------------------------------------------------------------------
__global__ void prescale_kernel(float* __restrict__ h, int N)
{
    int i = blockIdx.x * blockDim.x + threadIdx.x;       // float4 index
    int total = N * (N_CLASS / 4);
    if (i >= total) return;
    int n = i / (N_CLASS / 4);
    float sc = guarded_rsqrt(__ldg(deg_out_ptr() + n));
    float4 v = ((float4*)h)[i];
    v.x *= sc; v.y *= sc; v.z *= sc; v.w *= sc;
    ((float4*)h)[i] = v;
}

// ---------------------------------------------------------------------------
// 4) Pull-style hop — the R9-proven formulation: warp = 3 dst nodes, 10
//    lanes (float4 segment) each; plain unroll-4 __ldg loads (ptxas batches).
//    Scale/bias loads hoisted ABOVE the loop (loop-independent; trims the
//    store's dependency tail). Per-dst output scale: rsqrt(deg_in[d])
//    (* rsqrt(deg_out[d]) on the mid hop).
// ---------------------------------------------------------------------------
#define HOP_T 256   // 8 warps * 3 dsts = 24 dsts per block

__global__ void __launch_bounds__(HOP_T)
hop_csr_kernel(const float* __restrict__ hin,
               float* __restrict__ hout,
               const float* __restrict__ bias,
               int mul_rs_out,     // 1 for hop1 (mid), 0 for final hop
               int N)
{
    int warp = (blockIdx.x * HOP_T + threadIdx.x) >> 5;
    int lane = threadIdx.x & 31;
    int slot = lane / 10;          // 0..2 (lanes 30,31 idle)
    int seg  = lane - slot * 10;   // 0..9
    int d    = warp * 3 + slot;
    if (slot >= 3 || d >= N) return;

    int cnt = __ldg(cnt_ptr() + d);
    cnt = (cnt > MAX_DEG) ? MAX_DEG : cnt;

    // hoisted, loop-independent
    float sc = guarded_rsqrt(__ldg(deg_in_ptr() + d));
    if (mul_rs_out) sc *= guarded_rsqrt(__ldg(deg_out_ptr() + d));
    float4 bv = bias ? *(const float4*)(bias + seg * 4)
                     : make_float4(0.f, 0.f, 0.f, 0.f);

    const int4* lst4 = (const int4*)&g_csr[(size_t)d * MAX_DEG];

    float4 acc = make_float4(0.f, 0.f, 0.f, 0.f);

    int pairs = cnt >> 1;
#pragma unroll 4
    for (int i = 0; i < pairs; i++) {
        int4 pp = __ldg(lst4 + i);               // (s0, w0, s1, w1) raw
        float w0 = __int_as_float(pp.y);
        float w1 = __int_as_float(pp.w);
        float4 v0 = *(const float4*)(hin + (size_t)pp.x * N_CLASS + seg * 4);
        float4 v1 = *(const float4*)(hin + (size_t)pp.z * N_CLASS + seg * 4);
        acc.x += w0 * v0.x + w1 * v1.x;
        acc.y += w0 * v0.y + w1 * v1.y;
        acc.z += w0 * v0.z + w1 * v1.z;
        acc.w += w0 * v0.w + w1 * v1.w;
    }
    if (cnt & 1) {
        int2 p = __ldg((const int2*)lst4 + (cnt - 1));
        float w = __int_as_float(p.y);
        float4 v = *(const float4*)(hin + (size_t)p.x * N_CLASS + seg * 4);
        acc.x += w * v.x; acc.y += w * v.y; acc.z += w * v.z; acc.w += w * v.w;
    }

    acc.x = acc.x * sc + bv.x;
    acc.y = acc.y * sc + bv.y;
    acc.z = acc.z * sc + bv.z;
    acc.w = acc.w * sc + bv.w;

    *(float4*)(hout + (size_t)d * N_CLASS + seg * 4) = acc;
}

// ---------------------------------------------------------------------------
// Launch. Graph:
//   s :  memset(meta) -> fork -> deg_fill -> join -> prescale -> hop1 -> hop2
//   s2:               \-> xw -----------------^
// ---------------------------------------------------------------------------
extern "C" void kernel_launch(void* const* d_in, const int* in_sizes, int n_in,
                              void* d_out, int out_size)
{
    const float* features = (const float*)d_in[0];
    const int*   src      = (const int*)  d_in[1];
    const int*   dst      = (const int*)  d_in[2];
    const float* ew       = (const float*)d_in[3];
    const float* W        = (const float*)d_in[4];
    const float* b        = (const float*)d_in[5];
    float*       out      = (float*)d_out;

    const int E = in_sizes[1];
    const int N = in_sizes[0] / D_FEAT;

    void *p_meta, *p_h0, *p_h1;
    cudaGetSymbolAddress(&p_meta, g_meta);
    cudaGetSymbolAddress(&p_h0,   g_h0);
    cudaGetSymbolAddress(&p_h1,   g_h1);

    static cudaStream_t s2 = nullptr;
    static cudaEvent_t ev_fork = nullptr, ev_join = nullptr;
    if (s2 == nullptr) {
        cudaStreamCreateWithFlags(&s2, cudaStreamNonBlocking);
        cudaEventCreateWithFlags(&ev_fork, cudaEventDisableTiming);
        cudaEventCreateWithFlags(&ev_join, cudaEventDisableTiming);
    }

    cudaStream_t s = 0;
    const int T = 256;

    cudaMemsetAsync(p_meta, 0, (size_t)3 * N_NODES * sizeof(unsigned), s);

    // ---- fork ----
    cudaEventRecord(ev_fork, s);
    cudaStreamWaitEvent(s2, ev_fork, 0);

    // branch B: degrees + adjacency build (single edge pass)
    deg_fill_kernel<<<(E + T - 1) / T, T, 0, s>>>(src, dst, ew, E);

    // branch A: projection
    xw_kernel<<<(N + XW_M - 1) / XW_M, XW_T, 0, s2>>>(
        features, W, (float*)p_h0, N);

    // ---- join ----
    cudaEventRecord(ev_join, s2);
    cudaStreamWaitEvent(s, ev_join, 0);

    // pre-scale h0 rows by rsqrt(deg_out)
    {
        int total = N * (N_CLASS / 4);
        prescale_kernel<<<(total + T - 1) / T, T, 0, s>>>((float*)p_h0, N);
    }

    // hop 1 (mid): out-scale rs_in*rs_out ; hop 2 (final): rs_in, + bias
    int hop_blocks = (N + 23) / 24;
    hop_csr_kernel<<<hop_blocks, HOP_T, 0, s>>>(
        (const float*)p_h0, (float*)p_h1, nullptr, 1, N);
    hop_csr_kernel<<<hop_blocks, HOP_T, 0, s>>>(
        (const float*)p_h1, out, b, 0, N);
}

// round 15
// speedup vs baseline: 1.1340x; 1.0431x over previous
#include <cuda_runtime.h>
#include <cstdint>
#include <cstddef>

// SGCEvaluator: N=100000, E=1600000, D=128, C=40, 2 hops.
// (A^2 X) W + b == A^2 (X W) + b  -> project FIRST, hop on 40 dims.
// Normalization factored into per-NODE diagonal scales (rsqrt on the fly):
//   A^2 h0 = R_in * Wraw * (R_in R_out) * Wraw * (R_out * h0)
// This is the R9-proven configuration (141.8us) restored exactly: four
// subsequent hop-loop variants (prefetch chain, flat lane map, double-wide
// threads, scale/bias hoist) each regressed 3-19us via reduced MLP batching,
// occupancy loss, or L1 packing. regs=32 / occ~83% is the operating point.
#define N_NODES 100000
#define N_EDGES 1600000
#define D_FEAT  128
#define N_CLASS 40
#define MAX_DEG 64   // P(in-deg >= 64 | Poisson(16)) ~ 1e-18 per node

// Single contiguous meta slab -> ONE memset:
//   [0, N) float deg_out | [N, 2N) float deg_in | [2N, 3N) int cnt
__device__ __align__(256) unsigned g_meta[3 * N_NODES];
__device__ __align__(256) int2  g_csr[(size_t)N_NODES * MAX_DEG];  // (src, raw ew)
__device__ __align__(256) float g_h0 [(size_t)N_NODES * N_CLASS];
__device__ __align__(256) float g_h1 [(size_t)N_NODES * N_CLASS];

__device__ __forceinline__ float* deg_out_ptr() { return (float*)g_meta; }
__device__ __forceinline__ float* deg_in_ptr()  { return (float*)g_meta + N_NODES; }
__device__ __forceinline__ int*   cnt_ptr()     { return (int*)g_meta + 2 * N_NODES; }

__device__ __forceinline__ float guarded_rsqrt(float v)
{
    return (v > 0.f) ? rsqrtf(v) : 0.f;
}

// ---------------------------------------------------------------------------
// 1) Degrees + inverted-adjacency build in ONE edge pass (raw weights).
// ---------------------------------------------------------------------------
__global__ void deg_fill_kernel(const int* __restrict__ src,
                                const int* __restrict__ dst,
                                const float* __restrict__ ew,
                                int E)
{
    int e = blockIdx.x * blockDim.x + threadIdx.x;
    if (e >= E) return;

    int   s = src[e];
    int   d = dst[e];
    float w = ew[e];

    atomicAdd(deg_out_ptr() + s, w);
    atomicAdd(deg_in_ptr()  + d, w);

    int pos = atomicAdd(cnt_ptr() + d, 1);
    if (pos < MAX_DEG)
        g_csr[(size_t)d * MAX_DEG + pos] = make_int2(s, __float_as_int(w));
}

// ---------------------------------------------------------------------------
// 2) X' = X @ W : 8x8 register tiles, double-buffered k-staging.
// ---------------------------------------------------------------------------
#define XW_M    256
#define XW_T    160
#define XW_KT   16
#define XW_ROW  260
#define XW_NF4  (XW_M * XW_KT / 4)            // 1024 float4 per stage
#define XW_RPT  ((XW_NF4 + XW_T - 1) / XW_T)  // 7

__global__ void __launch_bounds__(XW_T)
xw_kernel(const float* __restrict__ x,
          const float* __restrict__ W,
          float* __restrict__ xp,
          int N)
{
    __shared__ float Ws[D_FEAT * N_CLASS];
    __shared__ float xs[2][XW_KT][XW_ROW];

    const int t    = threadIdx.x;
    const int tx   = t >> 5;
    const int ty   = t & 31;
    const int nblk = blockIdx.x * XW_M;

    for (int i = t; i < D_FEAT * N_CLASS / 4; i += XW_T)
        ((float4*)Ws)[i] = ((const float4*)W)[i];

    float acc[8][8];
#pragma unroll
    for (int i = 0; i < 8; i++)
#pragma unroll
        for (int j = 0; j < 8; j++) acc[i][j] = 0.f;

    const float4* x4 = (const float4*)x;
    float4 tmp[XW_RPT];

    auto FETCH = [&](int kt) {
#pragma unroll
        for (int r = 0; r < XW_RPT; r++) {
            int j = t + r * XW_T;
            if (j < XW_NF4) {
                int n  = j >> 2;
                int kq = j & 3;
                int nn = nblk + n;
                tmp[r] = (nn < N) ? x4[(size_t)nn * 32 + kt * 4 + kq]
                                  : make_float4(0.f, 0.f, 0.f, 0.f);
            }
        }
    };
    auto STORE = [&](int buf) {
#pragma unroll
        for (int r = 0; r < XW_RPT; r++) {
            int j = t + r * XW_T;
            if (j < XW_NF4) {
                int n  = j >> 2;
                int kq = j & 3;
                xs[buf][kq * 4 + 0][n] = tmp[r].x;
                xs[buf][kq * 4 + 1][n] = tmp[r].y;
                xs[buf][kq * 4 + 2][n] = tmp[r].z;
                xs[buf][kq * 4 + 3][n] = tmp[r].w;
            }
        }
    };

    FETCH(0);
    STORE(0);
    __syncthreads();

    int buf = 0;
    for (int kt = 0; kt < D_FEAT / XW_KT; kt++) {
        if (kt < D_FEAT / XW_KT - 1) FETCH(kt + 1);

#pragma unroll
        for (int kk = 0; kk < XW_KT; kk++) {
            float4 a0 = *(const float4*)&xs[buf][kk][ty * 4];
            float4 a1 = *(const float4*)&xs[buf][kk][128 + ty * 4];
            const float* wr = &Ws[(kt * XW_KT + kk) * N_CLASS + tx * 8];
            float4 w0 = *(const float4*)(wr);
            float4 w1 = *(const float4*)(wr + 4);
            float xm[8] = {a0.x, a0.y, a0.z, a0.w, a1.x, a1.y, a1.z, a1.w};
            float wv[8] = {w0.x, w0.y, w0.z, w0.w, w1.x, w1.y, w1.z, w1.w};
#pragma unroll
            for (int i = 0; i < 8; i++)
#pragma unroll
                for (int j = 0; j < 8; j++)
                    acc[i][j] += xm[i] * wv[j];
        }

        if (kt < D_FEAT / XW_KT - 1) STORE(buf ^ 1);
        __syncthreads();
        buf ^= 1;
    }

#pragma unroll
    for (int i = 0; i < 8; i++) {
        int n = nblk + ((i < 4) ? (ty * 4 + i) : (128 + ty * 4 + i - 4));
        if (n < N) {
            float* o = xp + (size_t)n * N_CLASS + tx * 8;
            *(float4*)(o)     = make_float4(acc[i][0], acc[i][1], acc[i][2], acc[i][3]);
            *(float4*)(o + 4) = make_float4(acc[i][4], acc[i][5], acc[i][6], acc[i][7]);
        }
    }
}

// ---------------------------------------------------------------------------
// 3) Row scale: h0[n][*] *= rsqrt(deg_out[n])   (one float4 per thread)
// ---------------------------------------------------------------------------
__global__ void prescale_kernel(float* __restrict__ h, int N)
{
    int i = blockIdx.x * blockDim.x + threadIdx.x;       // float4 index
    int total = N * (N_CLASS / 4);
    if (i >= total) return;
    int n = i / (N_CLASS / 4);
    float sc = guarded_rsqrt(__ldg(deg_out_ptr() + n));
    float4 v = ((float4*)h)[i];
    v.x *= sc; v.y *= sc; v.z *= sc; v.w *= sc;
    ((float4*)h)[i] = v;
}

// ---------------------------------------------------------------------------
// 4) Pull-style hop (R9 formulation, verbatim). Warp = 3 dst nodes, 10 lanes
//    (float4 segment) each; plain unroll-4 __ldg loads (ptxas batches the
//    independent loads itself). Scale/bias applied AFTER the loop (keeps
//    regs at 32 -> occ ~83%). Per-dst output scale: rsqrt(deg_in[d])
//    (* rsqrt(deg_out[d]) on the mid hop). bias seeds the final output.
// ---------------------------------------------------------------------------
#define HOP_T 256   // 8 warps * 3 dsts = 24 dsts per block

__global__ void __launch_bounds__(HOP_T)
hop_csr_kernel(const float* __restrict__ hin,
               float* __restrict__ hout,
               const float* __restrict__ bias,
               int mul_rs_out,     // 1 for hop1 (mid), 0 for final hop
               int N)
{
    int warp = (blockIdx.x * HOP_T + threadIdx.x) >> 5;
    int lane = threadIdx.x & 31;
    int slot = lane / 10;          // 0..2 (lanes 30,31 idle)
    int seg  = lane - slot * 10;   // 0..9
    int d    = warp * 3 + slot;
    if (slot >= 3 || d >= N) return;

    int cnt = __ldg(cnt_ptr() + d);
    cnt = (cnt > MAX_DEG) ? MAX_DEG : cnt;

    const int4* lst4 = (const int4*)&g_csr[(size_t)d * MAX_DEG];

    float4 acc = make_float4(0.f, 0.f, 0.f, 0.f);

    int pairs = cnt >> 1;
#pragma unroll 4
    for (int i = 0; i < pairs; i++) {
        int4 pp = __ldg(lst4 + i);               // (s0, w0, s1, w1) raw
        float w0 = __int_as_float(pp.y);
        float w1 = __int_as_float(pp.w);
        float4 v0 = *(const float4*)(hin + (size_t)pp.x * N_CLASS + seg * 4);
        float4 v1 = *(const float4*)(hin + (size_t)pp.z * N_CLASS + seg * 4);
        acc.x += w0 * v0.x + w1 * v1.x;
        acc.y += w0 * v0.y + w1 * v1.y;
        acc.z += w0 * v0.z + w1 * v1.z;
        acc.w += w0 * v0.w + w1 * v1.w;
    }
    if (cnt & 1) {
        int2 p = __ldg((const int2*)lst4 + (cnt - 1));
        float w = __int_as_float(p.y);
        float4 v = *(const float4*)(hin + (size_t)p.x * N_CLASS + seg * 4);
        acc.x += w * v.x; acc.y += w * v.y; acc.z += w * v.z; acc.w += w * v.w;
    }

    float sc = guarded_rsqrt(__ldg(deg_in_ptr() + d));
    if (mul_rs_out) sc *= guarded_rsqrt(__ldg(deg_out_ptr() + d));
    acc.x *= sc; acc.y *= sc; acc.z *= sc; acc.w *= sc;

    if (bias) {
        float4 bv = *(const float4*)(bias + seg * 4);
        acc.x += bv.x; acc.y += bv.y; acc.z += bv.z; acc.w += bv.w;
    }

    *(float4*)(hout + (size_t)d * N_CLASS + seg * 4) = acc;
}

// ---------------------------------------------------------------------------
// Launch. Graph:
//   s :  memset(meta) -> fork -> deg_fill -> join -> prescale -> hop1 -> hop2
//   s2:               \-> xw -----------------^
// ---------------------------------------------------------------------------
extern "C" void kernel_launch(void* const* d_in, const int* in_sizes, int n_in,
                              void* d_out, int out_size)
{
    const float* features = (const float*)d_in[0];
    const int*   src      = (const int*)  d_in[1];
    const int*   dst      = (const int*)  d_in[2];
    const float* ew       = (const float*)d_in[3];
    const float* W        = (const float*)d_in[4];
    const float* b        = (const float*)d_in[5];
    float*       out      = (float*)d_out;

    const int E = in_sizes[1];
    const int N = in_sizes[0] / D_FEAT;

    void *p_meta, *p_h0, *p_h1;
    cudaGetSymbolAddress(&p_meta, g_meta);
    cudaGetSymbolAddress(&p_h0,   g_h0);
    cudaGetSymbolAddress(&p_h1,   g_h1);

    static cudaStream_t s2 = nullptr;
    static cudaEvent_t ev_fork = nullptr, ev_join = nullptr;
    if (s2 == nullptr) {
        cudaStreamCreateWithFlags(&s2, cudaStreamNonBlocking);
        cudaEventCreateWithFlags(&ev_fork, cudaEventDisableTiming);
        cudaEventCreateWithFlags(&ev_join, cudaEventDisableTiming);
    }

    cudaStream_t s = 0;
    const int T = 256;

    cudaMemsetAsync(p_meta, 0, (size_t)3 * N_NODES * sizeof(unsigned), s);

    // ---- fork ----
    cudaEventRecord(ev_fork, s);
    cudaStreamWaitEvent(s2, ev_fork, 0);

    // branch B: degrees + adjacency build (single edge pass)
    deg_fill_kernel<<<(E + T - 1) / T, T, 0, s>>>(src, dst, ew, E);

    // branch A: projection
    xw_kernel<<<(N + XW_M - 1) / XW_M, XW_T, 0, s2>>>(
        features, W, (float*)p_h0, N);

    // ---- join ----
    cudaEventRecord(ev_join, s2);
    cudaStreamWaitEvent(s, ev_join, 0);

    // pre-scale h0 rows by rsqrt(deg_out)
    {
        int total = N * (N_CLASS / 4);
        prescale_kernel<<<(total + T - 1) / T, T, 0, s>>>((float*)p_h0, N);
    }

    // hop 1 (mid): out-scale rs_in*rs_out ; hop 2 (final): rs_in, + bias
    int hop_blocks = (N + 23) / 24;
    hop_csr_kernel<<<hop_blocks, HOP_T, 0, s>>>(
        (const float*)p_h0, (float*)p_h1, nullptr, 1, N);
    hop_csr_kernel<<<hop_blocks, HOP_T, 0, s>>>(
        (const float*)p_h1, out, b, 0, N);
}

// round 16
// speedup vs baseline: 1.1506x; 1.0147x over previous
#include <cuda_runtime.h>
#include <cstdint>
#include <cstddef>

// SGCEvaluator: N=100000, E=1600000, D=128, C=40, 2 hops.
// (A^2 X) W + b == A^2 (X W) + b  -> project FIRST, hop on 40 dims.
// Normalization factored into per-NODE diagonal scales (rsqrt on the fly):
//   A^2 h0 = R_in * Wraw * (R_in R_out) * Wraw * (R_out * h0)
// R9-proven configuration; only change vs R15: hop block 256 -> 128 threads
// (same warp->3-dst mapping, same regs/occupancy, halved wave-tail quantum).
#define N_NODES 100000
#define N_EDGES 1600000
#define D_FEAT  128
#define N_CLASS 40
#define MAX_DEG 64   // P(in-deg >= 64 | Poisson(16)) ~ 1e-18 per node

// Single contiguous meta slab -> ONE memset:
//   [0, N) float deg_out | [N, 2N) float deg_in | [2N, 3N) int cnt
__device__ __align__(256) unsigned g_meta[3 * N_NODES];
__device__ __align__(256) int2  g_csr[(size_t)N_NODES * MAX_DEG];  // (src, raw ew)
__device__ __align__(256) float g_h0 [(size_t)N_NODES * N_CLASS];
__device__ __align__(256) float g_h1 [(size_t)N_NODES * N_CLASS];

__device__ __forceinline__ float* deg_out_ptr() { return (float*)g_meta; }
__device__ __forceinline__ float* deg_in_ptr()  { return (float*)g_meta + N_NODES; }
__device__ __forceinline__ int*   cnt_ptr()     { return (int*)g_meta + 2 * N_NODES; }

__device__ __forceinline__ float guarded_rsqrt(float v)
{
    return (v > 0.f) ? rsqrtf(v) : 0.f;
}

// ---------------------------------------------------------------------------
// 1) Degrees + inverted-adjacency build in ONE edge pass (raw weights).
// ---------------------------------------------------------------------------
__global__ void deg_fill_kernel(const int* __restrict__ src,
                                const int* __restrict__ dst,
                                const float* __restrict__ ew,
                                int E)
{
    int e = blockIdx.x * blockDim.x + threadIdx.x;
    if (e >= E) return;

    int   s = src[e];
    int   d = dst[e];
    float w = ew[e];

    atomicAdd(deg_out_ptr() + s, w);
    atomicAdd(deg_in_ptr()  + d, w);

    int pos = atomicAdd(cnt_ptr() + d, 1);
    if (pos < MAX_DEG)
        g_csr[(size_t)d * MAX_DEG + pos] = make_int2(s, __float_as_int(w));
}

// ---------------------------------------------------------------------------
// 2) X' = X @ W : 8x8 register tiles, double-buffered k-staging.
// ---------------------------------------------------------------------------
#define XW_M    256
#define XW_T    160
#define XW_KT   16
#define XW_ROW  260
#define XW_NF4  (XW_M * XW_KT / 4)            // 1024 float4 per stage
#define XW_RPT  ((XW_NF4 + XW_T - 1) / XW_T)  // 7

__global__ void __launch_bounds__(XW_T)
xw_kernel(const float* __restrict__ x,
          const float* __restrict__ W,
          float* __restrict__ xp,
          int N)
{
    __shared__ float Ws[D_FEAT * N_CLASS];
    __shared__ float xs[2][XW_KT][XW_ROW];

    const int t    = threadIdx.x;
    const int tx   = t >> 5;
    const int ty   = t & 31;
    const int nblk = blockIdx.x * XW_M;

    for (int i = t; i < D_FEAT * N_CLASS / 4; i += XW_T)
        ((float4*)Ws)[i] = ((const float4*)W)[i];

    float acc[8][8];
#pragma unroll
    for (int i = 0; i < 8; i++)
#pragma unroll
        for (int j = 0; j < 8; j++) acc[i][j] = 0.f;

    const float4* x4 = (const float4*)x;
    float4 tmp[XW_RPT];

    auto FETCH = [&](int kt) {
#pragma unroll
        for (int r = 0; r < XW_RPT; r++) {
            int j = t + r * XW_T;
            if (j < XW_NF4) {
                int n  = j >> 2;
                int kq = j & 3;
                int nn = nblk + n;
                tmp[r] = (nn < N) ? x4[(size_t)nn * 32 + kt * 4 + kq]
                                  : make_float4(0.f, 0.f, 0.f, 0.f);
            }
        }
    };
    auto STORE = [&](int buf) {
#pragma unroll
        for (int r = 0; r < XW_RPT; r++) {
            int j = t + r * XW_T;
            if (j < XW_NF4) {
                int n  = j >> 2;
                int kq = j & 3;
                xs[buf][kq * 4 + 0][n] = tmp[r].x;
                xs[buf][kq * 4 + 1][n] = tmp[r].y;
                xs[buf][kq * 4 + 2][n] = tmp[r].z;
                xs[buf][kq * 4 + 3][n] = tmp[r].w;
            }
        }
    };

    FETCH(0);
    STORE(0);
    __syncthreads();

    int buf = 0;
    for (int kt = 0; kt < D_FEAT / XW_KT; kt++) {
        if (kt < D_FEAT / XW_KT - 1) FETCH(kt + 1);

#pragma unroll
        for (int kk = 0; kk < XW_KT; kk++) {
            float4 a0 = *(const float4*)&xs[buf][kk][ty * 4];
            float4 a1 = *(const float4*)&xs[buf][kk][128 + ty * 4];
            const float* wr = &Ws[(kt * XW_KT + kk) * N_CLASS + tx * 8];
            float4 w0 = *(const float4*)(wr);
            float4 w1 = *(const float4*)(wr + 4);
            float xm[8] = {a0.x, a0.y, a0.z, a0.w, a1.x, a1.y, a1.z, a1.w};
            float wv[8] = {w0.x, w0.y, w0.z, w0.w, w1.x, w1.y, w1.z, w1.w};
#pragma unroll
            for (int i = 0; i < 8; i++)
#pragma unroll
                for (int j = 0; j < 8; j++)
                    acc[i][j] += xm[i] * wv[j];
        }

        if (kt < D_FEAT / XW_KT - 1) STORE(buf ^ 1);
        __syncthreads();
        buf ^= 1;
    }

#pragma unroll
    for (int i = 0; i < 8; i++) {
        int n = nblk + ((i < 4) ? (ty * 4 + i) : (128 + ty * 4 + i - 4));
        if (n < N) {
            float* o = xp + (size_t)n * N_CLASS + tx * 8;
            *(float4*)(o)     = make_float4(acc[i][0], acc[i][1], acc[i][2], acc[i][3]);
            *(float4*)(o + 4) = make_float4(acc[i][4], acc[i][5], acc[i][6], acc[i][7]);
        }
    }
}

// ---------------------------------------------------------------------------
// 3) Row scale: h0[n][*] *= rsqrt(deg_out[n])   (one float4 per thread)
// ---------------------------------------------------------------------------
__global__ void prescale_kernel(float* __restrict__ h, int N)
{
    int i = blockIdx.x * blockDim.x + threadIdx.x;       // float4 index
    int total = N * (N_CLASS / 4);
    if (i >= total) return;
    int n = i / (N_CLASS / 4);
    float sc = guarded_rsqrt(__ldg(deg_out_ptr() + n));
    float4 v = ((float4*)h)[i];
    v.x *= sc; v.y *= sc; v.z *= sc; v.w *= sc;
    ((float4*)h)[i] = v;
}

// ---------------------------------------------------------------------------
// 4) Pull-style hop (R9 body, verbatim). Warp = 3 dst nodes, 10 lanes
//    (float4 segment) each; plain unroll-4 __ldg loads (ptxas batches).
//    ONLY change: 128-thread blocks (4 warps = 12 dsts/block) -> halved
//    wave-tail quantum at identical regs/thread-occupancy.
// ---------------------------------------------------------------------------
#define HOP_T 128   // 4 warps * 3 dsts = 12 dsts per block

__global__ void __launch_bounds__(HOP_T)
hop_csr_kernel(const float* __restrict__ hin,
               float* __restrict__ hout,
               const float* __restrict__ bias,
               int mul_rs_out,     // 1 for hop1 (mid), 0 for final hop
               int N)
{
    int warp = (blockIdx.x * HOP_T + threadIdx.x) >> 5;
    int lane = threadIdx.x & 31;
    int slot = lane / 10;          // 0..2 (lanes 30,31 idle)
    int seg  = lane - slot * 10;   // 0..9
    int d    = warp * 3 + slot;
    if (slot >= 3 || d >= N) return;

    int cnt = __ldg(cnt_ptr() + d);
    cnt = (cnt > MAX_DEG) ? MAX_DEG : cnt;

    const int4* lst4 = (const int4*)&g_csr[(size_t)d * MAX_DEG];

    float4 acc = make_float4(0.f, 0.f, 0.f, 0.f);

    int pairs = cnt >> 1;
#pragma unroll 4
    for (int i = 0; i < pairs; i++) {
        int4 pp = __ldg(lst4 + i);               // (s0, w0, s1, w1) raw
        float w0 = __int_as_float(pp.y);
        float w1 = __int_as_float(pp.w);
        float4 v0 = *(const float4*)(hin + (size_t)pp.x * N_CLASS + seg * 4);
        float4 v1 = *(const float4*)(hin + (size_t)pp.z * N_CLASS + seg * 4);
        acc.x += w0 * v0.x + w1 * v1.x;
        acc.y += w0 * v0.y + w1 * v1.y;
        acc.z += w0 * v0.z + w1 * v1.z;
        acc.w += w0 * v0.w + w1 * v1.w;
    }
    if (cnt & 1) {
        int2 p = __ldg((const int2*)lst4 + (cnt - 1));
        float w = __int_as_float(p.y);
        float4 v = *(const float4*)(hin + (size_t)p.x * N_CLASS + seg * 4);
        acc.x += w * v.x; acc.y += w * v.y; acc.z += w * v.z; acc.w += w * v.w;
    }

    float sc = guarded_rsqrt(__ldg(deg_in_ptr() + d));
    if (mul_rs_out) sc *= guarded_rsqrt(__ldg(deg_out_ptr() + d));
    acc.x *= sc; acc.y *= sc; acc.z *= sc; acc.w *= sc;

    if (bias) {
        float4 bv = *(const float4*)(bias + seg * 4);
        acc.x += bv.x; acc.y += bv.y; acc.z += bv.z; acc.w += bv.w;
    }

    *(float4*)(hout + (size_t)d * N_CLASS + seg * 4) = acc;
}

// ---------------------------------------------------------------------------
// Launch. Graph:
//   s :  memset(meta) -> fork -> deg_fill -> join -> prescale -> hop1 -> hop2
//   s2:               \-> xw -----------------^
// ---------------------------------------------------------------------------
extern "C" void kernel_launch(void* const* d_in, const int* in_sizes, int n_in,
                              void* d_out, int out_size)
{
    const float* features = (const float*)d_in[0];
    const int*   src      = (const int*)  d_in[1];
    const int*   dst      = (const int*)  d_in[2];
    const float* ew       = (const float*)d_in[3];
    const float* W        = (const float*)d_in[4];
    const float* b        = (const float*)d_in[5];
    float*       out      = (float*)d_out;

    const int E = in_sizes[1];
    const int N = in_sizes[0] / D_FEAT;

    void *p_meta, *p_h0, *p_h1;
    cudaGetSymbolAddress(&p_meta, g_meta);
    cudaGetSymbolAddress(&p_h0,   g_h0);
    cudaGetSymbolAddress(&p_h1,   g_h1);

    static cudaStream_t s2 = nullptr;
    static cudaEvent_t ev_fork = nullptr, ev_join = nullptr;
    if (s2 == nullptr) {
        cudaStreamCreateWithFlags(&s2, cudaStreamNonBlocking);
        cudaEventCreateWithFlags(&ev_fork, cudaEventDisableTiming);
        cudaEventCreateWithFlags(&ev_join, cudaEventDisableTiming);
    }

    cudaStream_t s = 0;
    const int T = 256;

    cudaMemsetAsync(p_meta, 0, (size_t)3 * N_NODES * sizeof(unsigned), s);

    // ---- fork ----
    cudaEventRecord(ev_fork, s);
    cudaStreamWaitEvent(s2, ev_fork, 0);

    // branch B: degrees + adjacency build (single edge pass)
    deg_fill_kernel<<<(E + T - 1) / T, T, 0, s>>>(src, dst, ew, E);

    // branch A: projection
    xw_kernel<<<(N + XW_M - 1) / XW_M, XW_T, 0, s2>>>(
        features, W, (float*)p_h0, N);

    // ---- join ----
    cudaEventRecord(ev_join, s2);
    cudaStreamWaitEvent(s, ev_join, 0);

    // pre-scale h0 rows by rsqrt(deg_out)
    {
        int total = N * (N_CLASS / 4);
        prescale_kernel<<<(total + T - 1) / T, T, 0, s>>>((float*)p_h0, N);
    }

    // hop 1 (mid): out-scale rs_in*rs_out ; hop 2 (final): rs_in, + bias
    int hop_blocks = (N + 11) / 12;     // 12 dsts per 128-thread block
    hop_csr_kernel<<<hop_blocks, HOP_T, 0, s>>>(
        (const float*)p_h0, (float*)p_h1, nullptr, 1, N);
    hop_csr_kernel<<<hop_blocks, HOP_T, 0, s>>>(
        (const float*)p_h1, out, b, 0, N);
}